// round 1
// baseline (speedup 1.0000x reference)
#include <cuda_runtime.h>

// Problem shapes (fixed by the reference):
//   content [64, 256], motion [64, 512, 128]  -> tokens M = 64*512 = 32768
//   L1: [M,384] x [384,256] + b1, leaky(0.2)
//   L2: [M,256] x [256,512] + b2, leaky(0.2)
//   L3: [M,512] x [512,1152] + b3
// Output: [M, 1152] fp32.

#define BM 128
#define BN 128
#define BK 16
#define NTHREADS 256

// Inter-layer scratch (allowed: static __device__ arrays, not runtime allocs).
__device__ float g_h1[32768 * 256];   // 33.5 MB
__device__ float g_h2[32768 * 512];   // 67 MB

__device__ __forceinline__ float leaky02(float x) {
    return x >= 0.0f ? x : 0.2f * x;
}

// Classic 128x128x16 tiled SGEMM, 256 threads, 8x8 micro-tile per thread with
// split 4+4 fragment mapping (rows {tr*4, 64+tr*4}, cols {tc*4, 64+tc*4}) so
// LDS.128 fragment loads are bank-conflict-free.
// CONCAT: A is the virtual [M,384] concat of content (k<256) and motion (k>=256).
//         BK=16 divides 256, so every K-tile lies entirely on one side.
template<bool CONCAT, bool LEAKY>
__global__ __launch_bounds__(NTHREADS)
void mlp_gemm(const float* __restrict__ A,
              const float* __restrict__ content,
              const float* __restrict__ motion,
              const float* __restrict__ W,
              const float* __restrict__ bias,
              float* __restrict__ C,
              int M, int N, int K)
{
    __shared__ float As[BK][BM + 4];  // padded: A-store write pattern spreads banks
    __shared__ float Ws[BK][BN];

    const int tid = threadIdx.x;
    const int rowBlock = blockIdx.y * BM;
    const int colBlock = blockIdx.x * BN;

    const int tr = tid / 16;   // 0..15
    const int tc = tid % 16;   // 0..15

    float acc[8][8];
    #pragma unroll
    for (int i = 0; i < 8; i++)
        #pragma unroll
        for (int j = 0; j < 8; j++) acc[i][j] = 0.0f;

    // A-tile loader mapping: 256 threads * 2 iters * float4 = 128 rows x 16 k
    const int aRow  = tid / 4;         // 0..63
    const int aCol4 = (tid % 4) * 4;   // 0,4,8,12
    // W-tile loader mapping: 256 threads * 2 iters * float4 = 16 k x 128 cols
    const int wRow  = tid / 32;        // 0..7
    const int wCol4 = (tid % 32) * 4;  // 0..124

    for (int k0 = 0; k0 < K; k0 += BK) {
        // ---- Load A tile, store transposed As[k][m] ----
        #pragma unroll
        for (int it = 0; it < 2; ++it) {
            const int grow = rowBlock + aRow + it * 64;
            const int gk = k0 + aCol4;
            float4 v;
            if (CONCAT) {
                if (gk < 256) {
                    // content row reused across all 512 timesteps of a batch item
                    v = *reinterpret_cast<const float4*>(
                        &content[(size_t)(grow >> 9) * 256 + gk]);
                } else {
                    v = *reinterpret_cast<const float4*>(
                        &motion[(size_t)grow * 128 + (gk - 256)]);
                }
            } else {
                v = *reinterpret_cast<const float4*>(&A[(size_t)grow * K + gk]);
            }
            As[aCol4 + 0][aRow + it * 64] = v.x;
            As[aCol4 + 1][aRow + it * 64] = v.y;
            As[aCol4 + 2][aRow + it * 64] = v.z;
            As[aCol4 + 3][aRow + it * 64] = v.w;
        }
        // ---- Load W tile (natural layout Ws[k][n]) ----
        #pragma unroll
        for (int it = 0; it < 2; ++it) {
            const int gk = k0 + wRow + it * 8;
            const float4 v = *reinterpret_cast<const float4*>(
                &W[(size_t)gk * N + colBlock + wCol4]);
            *reinterpret_cast<float4*>(&Ws[wRow + it * 8][wCol4]) = v;
        }
        __syncthreads();

        // ---- 16 rank-1 updates ----
        #pragma unroll
        for (int k = 0; k < BK; ++k) {
            float ra[8], rb[8];
            // split fragments: conflict-free 128b shared loads
            *reinterpret_cast<float4*>(&ra[0]) =
                *reinterpret_cast<const float4*>(&As[k][tr * 4]);
            *reinterpret_cast<float4*>(&ra[4]) =
                *reinterpret_cast<const float4*>(&As[k][64 + tr * 4]);
            *reinterpret_cast<float4*>(&rb[0]) =
                *reinterpret_cast<const float4*>(&Ws[k][tc * 4]);
            *reinterpret_cast<float4*>(&rb[4]) =
                *reinterpret_cast<const float4*>(&Ws[k][64 + tc * 4]);
            #pragma unroll
            for (int i = 0; i < 8; ++i)
                #pragma unroll
                for (int j = 0; j < 8; ++j)
                    acc[i][j] = fmaf(ra[i], rb[j], acc[i][j]);
        }
        __syncthreads();
    }

    // ---- Epilogue: bias (+ leaky), vectorized stores ----
    #pragma unroll
    for (int i = 0; i < 8; ++i) {
        const int grow = rowBlock + (i < 4 ? (tr * 4 + i) : (64 + tr * 4 + (i - 4)));
        #pragma unroll
        for (int jh = 0; jh < 2; ++jh) {
            const int gcol = colBlock + (jh == 0 ? (tc * 4) : (64 + tc * 4));
            float4 v;
            v.x = acc[i][jh * 4 + 0] + bias[gcol + 0];
            v.y = acc[i][jh * 4 + 1] + bias[gcol + 1];
            v.z = acc[i][jh * 4 + 2] + bias[gcol + 2];
            v.w = acc[i][jh * 4 + 3] + bias[gcol + 3];
            if (LEAKY) {
                v.x = leaky02(v.x); v.y = leaky02(v.y);
                v.z = leaky02(v.z); v.w = leaky02(v.w);
            }
            *reinterpret_cast<float4*>(&C[(size_t)grow * N + gcol]) = v;
        }
    }
}

extern "C" void kernel_launch(void* const* d_in, const int* in_sizes, int n_in,
                              void* d_out, int out_size)
{
    (void)in_sizes; (void)n_in; (void)out_size;
    const float* content = (const float*)d_in[0];  // [64,256]
    const float* motion  = (const float*)d_in[1];  // [64,512,128]
    const float* W1 = (const float*)d_in[2];       // [384,256]
    const float* b1 = (const float*)d_in[3];
    const float* W2 = (const float*)d_in[4];       // [256,512]
    const float* b2 = (const float*)d_in[5];
    const float* W3 = (const float*)d_in[6];       // [512,1152]
    const float* b3 = (const float*)d_in[7];
    float* out = (float*)d_out;                    // [32768,1152]

    float* h1 = nullptr;
    float* h2 = nullptr;
    cudaGetSymbolAddress((void**)&h1, g_h1);
    cudaGetSymbolAddress((void**)&h2, g_h2);

    const int M = 32768;

    // L1: [M,384] x [384,256] -> h1, leaky
    mlp_gemm<true, true><<<dim3(256 / BN, M / BM), NTHREADS>>>(
        nullptr, content, motion, W1, b1, h1, M, 256, 384);
    // L2: [M,256] x [256,512] -> h2, leaky
    mlp_gemm<false, true><<<dim3(512 / BN, M / BM), NTHREADS>>>(
        h1, nullptr, nullptr, W2, b2, h2, M, 512, 256);
    // L3: [M,512] x [512,1152] -> out
    mlp_gemm<false, false><<<dim3(1152 / BN, M / BM), NTHREADS>>>(
        h2, nullptr, nullptr, W3, b3, out, M, 1152, 512);
}

// round 3
// speedup vs baseline: 1.5807x; 1.5807x over previous
#include <cuda_runtime.h>
#include <cuda_bf16.h>
#include <cstdint>

// ============================================================================
// Problem: content[64,256], motion[64,512,128] -> M=32768 tokens
//   L1: [M,384]x[384,256]+b1, leaky(0.2)
//   L2: [M,256]x[256,512]+b2, leaky(0.2)
//   L3: [M,512]x[512,1152]+b3 -> out fp32
// Strategy: bf16x3 emulated-fp32 GEMM on mma.sync.m16n8k16 (HMMA tensor pipe).
//   (tcgen05 is unavailable: harness PTX target is compute_103, no 'a' suffix.)
//   Every operand split x = hi + lo (bf16 each); C = A1*B1 + A2*B1 + A1*B2.
// ============================================================================

// ---- device scratch (static arrays: runtime allocation is forbidden) ----
__device__ __nv_bfloat16 g_a1hi[12582912];   // [32768,384]
__device__ __nv_bfloat16 g_a1lo[12582912];
__device__ __nv_bfloat16 g_h1hi[8388608];    // [32768,256]
__device__ __nv_bfloat16 g_h1lo[8388608];
__device__ __nv_bfloat16 g_h2hi[16777216];   // [32768,512]
__device__ __nv_bfloat16 g_h2lo[16777216];
__device__ __nv_bfloat16 g_w1hi[98304],  g_w1lo[98304];    // [256,384]  (N,K)
__device__ __nv_bfloat16 g_w2hi[131072], g_w2lo[131072];   // [512,256]
__device__ __nv_bfloat16 g_w3hi[589824], g_w3lo[589824];   // [1152,512]

// ---- helpers ----
__device__ __forceinline__ uint32_t smem_u32(const void* p) {
    uint32_t a;
    asm("{ .reg .u64 t; cvta.to.shared.u64 t, %1; cvt.u32.u64 %0, t; }"
        : "=r"(a) : "l"(p));
    return a;
}
__device__ __forceinline__ void cp16(uint32_t dst, const void* src) {
    asm volatile("cp.async.cg.shared.global [%0], [%1], 16;"
                 :: "r"(dst), "l"(src) : "memory");
}
#define CP_COMMIT() asm volatile("cp.async.commit_group;" ::: "memory")
#define CP_WAIT(n)  asm volatile("cp.async.wait_group %0;" :: "n"(n) : "memory")

// D = A*B + D  (m16n8k16, bf16 in, fp32 acc)
__device__ __forceinline__ void hmma(float* c, const uint32_t* a, const uint32_t* b) {
    asm volatile(
        "mma.sync.aligned.m16n8k16.row.col.f32.bf16.bf16.f32 "
        "{%0,%1,%2,%3}, {%4,%5,%6,%7}, {%8,%9}, {%0,%1,%2,%3};"
        : "+f"(c[0]), "+f"(c[1]), "+f"(c[2]), "+f"(c[3])
        : "r"(a[0]), "r"(a[1]), "r"(a[2]), "r"(a[3]), "r"(b[0]), "r"(b[1]));
}

// ============================================================================
// Split/prep kernels
// ============================================================================
__global__ void prep_a(const float* __restrict__ content,
                       const float* __restrict__ motion,
                       __nv_bfloat16* __restrict__ hi,
                       __nv_bfloat16* __restrict__ lo)
{
    int idx = blockIdx.x * 256 + threadIdx.x;
    if (idx >= 32768 * 384) return;
    int m = idx / 384, k = idx - m * 384;
    float v = (k < 256) ? content[(m >> 9) * 256 + k]
                        : motion[(size_t)m * 128 + (k - 256)];
    __nv_bfloat16 h = __float2bfloat16(v);
    hi[idx] = h;
    lo[idx] = __float2bfloat16(v - __bfloat162float(h));
}

// W[K,N] row-major -> Wt[N,K] hi/lo (K-major; matches mma.sync B "col" layout)
__global__ void prep_w(const float* __restrict__ W,
                       __nv_bfloat16* __restrict__ hi,
                       __nv_bfloat16* __restrict__ lo, int N, int K)
{
    int idx = blockIdx.x * 256 + threadIdx.x;
    if (idx >= N * K) return;
    int n = idx / K, k = idx - n * K;
    float v = W[(size_t)k * N + n];
    __nv_bfloat16 h = __float2bfloat16(v);
    hi[idx] = h;
    lo[idx] = __float2bfloat16(v - __bfloat162float(h));
}

// ============================================================================
// bf16x3 GEMM: CTA tile 128x128, BK=32 chunks, NC = 3*K/32 chunk stream
//   pass0: Ahi*Bhi   pass1: Alo*Bhi   pass2: Ahi*Blo   (fp32 accum in regs)
// 256 threads = 8 warps, warp grid 2(M)x4(N), warp tile 64x32.
// SMEM rows padded to 40 bf16 (80B): conflict-free 32b fragment LDS + 16B cp.
// ============================================================================
#define PADK 40

template<int K, int NTOT, bool LEAKY, bool WRITE_F32>
__global__ __launch_bounds__(256, 2)
void gemm_hmma(const __nv_bfloat16* __restrict__ Ahi,
               const __nv_bfloat16* __restrict__ Alo,
               const __nv_bfloat16* __restrict__ Bhi,
               const __nv_bfloat16* __restrict__ Blo,
               const float* __restrict__ bias,
               float* __restrict__ Cout,
               __nv_bfloat16* __restrict__ NxtHi,
               __nv_bfloat16* __restrict__ NxtLo)
{
    constexpr int KC = K / 32;
    constexpr int NC = 3 * KC;

    __shared__ __nv_bfloat16 As[2][128][PADK];
    __shared__ __nv_bfloat16 Bs[2][128][PADK];

    const int tid  = threadIdx.x;
    const int lane = tid & 31;
    const int wid  = tid >> 5;
    const int g    = lane >> 2;        // 0..7
    const int t4   = lane & 3;         // 0..3
    const int t2   = t4 * 2;
    const int wm   = (wid >> 2) * 64;  // warp M offset (0,64)
    const int wn   = (wid & 3) * 32;   // warp N offset (0,32,64,96)

    const int rowBlock = blockIdx.y * 128;
    const int colBlock = blockIdx.x * 128;

    float acc[4][4][4];
    #pragma unroll
    for (int i = 0; i < 4; i++)
        #pragma unroll
        for (int j = 0; j < 4; j++)
            #pragma unroll
            for (int r = 0; r < 4; r++) acc[i][j][r] = 0.0f;

    // cp.async loader mapping: 512 16B-chunks per tile, 2 per thread per tile
    const int ldRow0 = tid >> 2;            // (i*256+tid)>>2 for i=0
    const int ldCh0  = tid & 3;
    // i=1: rows 64..127
    auto issue_chunk = [&](int c) {
        const int pass = c / KC;
        const int kk   = c - pass * KC;
        const __nv_bfloat16* Aop = (pass == 1) ? Alo : Ahi;
        const __nv_bfloat16* Bop = (pass == 2) ? Blo : Bhi;
        const int k0  = kk * 32;
        const int buf = c & 1;
        #pragma unroll
        for (int i = 0; i < 2; ++i) {
            const int row = ldRow0 + i * 64;
            const int ch  = ldCh0;
            cp16(smem_u32(&As[buf][row][ch * 8]),
                 Aop + (size_t)(rowBlock + row) * K + k0 + ch * 8);
            cp16(smem_u32(&Bs[buf][row][ch * 8]),
                 Bop + (size_t)(colBlock + row) * K + k0 + ch * 8);
        }
        CP_COMMIT();
    };

    issue_chunk(0);

    for (int c = 0; c < NC; ++c) {
        if (c + 1 < NC) {
            issue_chunk(c + 1);
            CP_WAIT(1);
        } else {
            CP_WAIT(0);
        }
        __syncthreads();

        const int buf = c & 1;
        #pragma unroll
        for (int ks = 0; ks < 2; ++ks) {
            const int kb = ks * 16;
            uint32_t a[4][4], b[4][2];
            #pragma unroll
            for (int mt = 0; mt < 4; ++mt) {
                const int r0 = wm + mt * 16 + g;
                a[mt][0] = *reinterpret_cast<const uint32_t*>(&As[buf][r0][kb + t2]);
                a[mt][1] = *reinterpret_cast<const uint32_t*>(&As[buf][r0 + 8][kb + t2]);
                a[mt][2] = *reinterpret_cast<const uint32_t*>(&As[buf][r0][kb + t2 + 8]);
                a[mt][3] = *reinterpret_cast<const uint32_t*>(&As[buf][r0 + 8][kb + t2 + 8]);
            }
            #pragma unroll
            for (int nt = 0; nt < 4; ++nt) {
                const int n0 = wn + nt * 8 + g;
                b[nt][0] = *reinterpret_cast<const uint32_t*>(&Bs[buf][n0][kb + t2]);
                b[nt][1] = *reinterpret_cast<const uint32_t*>(&Bs[buf][n0][kb + t2 + 8]);
            }
            #pragma unroll
            for (int mt = 0; mt < 4; ++mt)
                #pragma unroll
                for (int nt = 0; nt < 4; ++nt)
                    hmma(acc[mt][nt], a[mt], b[nt]);
        }
        __syncthreads();
    }

    // ---- epilogue: bias (+leaky) -> fp32 out, or bf16 hi/lo split for next ----
    #pragma unroll
    for (int mt = 0; mt < 4; ++mt) {
        #pragma unroll
        for (int half = 0; half < 2; ++half) {
            const int grow = rowBlock + wm + mt * 16 + g + half * 8;
            #pragma unroll
            for (int nt = 0; nt < 4; ++nt) {
                const int gcol = colBlock + wn + nt * 8 + t2;
                float v0 = acc[mt][nt][half * 2 + 0] + bias[gcol];
                float v1 = acc[mt][nt][half * 2 + 1] + bias[gcol + 1];
                if (LEAKY) {
                    v0 = v0 >= 0.f ? v0 : 0.2f * v0;
                    v1 = v1 >= 0.f ? v1 : 0.2f * v1;
                }
                const size_t base = (size_t)grow * NTOT + gcol;
                if (WRITE_F32) {
                    float2 o; o.x = v0; o.y = v1;
                    *reinterpret_cast<float2*>(&Cout[base]) = o;
                } else {
                    __nv_bfloat16 h0 = __float2bfloat16(v0);
                    __nv_bfloat16 h1 = __float2bfloat16(v1);
                    __nv_bfloat16 l0 = __float2bfloat16(v0 - __bfloat162float(h0));
                    __nv_bfloat16 l1 = __float2bfloat16(v1 - __bfloat162float(h1));
                    *reinterpret_cast<__nv_bfloat162*>(&NxtHi[base]) =
                        __halves2bfloat162(h0, h1);
                    *reinterpret_cast<__nv_bfloat162*>(&NxtLo[base]) =
                        __halves2bfloat162(l0, l1);
                }
            }
        }
    }
}

// ============================================================================
// launcher
// ============================================================================
extern "C" void kernel_launch(void* const* d_in, const int* in_sizes, int n_in,
                              void* d_out, int out_size)
{
    (void)in_sizes; (void)n_in; (void)out_size;
    const float* content = (const float*)d_in[0];
    const float* motion  = (const float*)d_in[1];
    const float* W1 = (const float*)d_in[2];
    const float* b1 = (const float*)d_in[3];
    const float* W2 = (const float*)d_in[4];
    const float* b2 = (const float*)d_in[5];
    const float* W3 = (const float*)d_in[6];
    const float* b3 = (const float*)d_in[7];
    float* out = (float*)d_out;

    __nv_bfloat16 *a1hi, *a1lo, *h1hi, *h1lo, *h2hi, *h2lo;
    __nv_bfloat16 *w1hi, *w1lo, *w2hi, *w2lo, *w3hi, *w3lo;
    cudaGetSymbolAddress((void**)&a1hi, g_a1hi);
    cudaGetSymbolAddress((void**)&a1lo, g_a1lo);
    cudaGetSymbolAddress((void**)&h1hi, g_h1hi);
    cudaGetSymbolAddress((void**)&h1lo, g_h1lo);
    cudaGetSymbolAddress((void**)&h2hi, g_h2hi);
    cudaGetSymbolAddress((void**)&h2lo, g_h2lo);
    cudaGetSymbolAddress((void**)&w1hi, g_w1hi);
    cudaGetSymbolAddress((void**)&w1lo, g_w1lo);
    cudaGetSymbolAddress((void**)&w2hi, g_w2hi);
    cudaGetSymbolAddress((void**)&w2lo, g_w2lo);
    cudaGetSymbolAddress((void**)&w3hi, g_w3hi);
    cudaGetSymbolAddress((void**)&w3lo, g_w3lo);

    // ---- prep: split inputs/weights into bf16 hi/lo ----
    prep_a<<<(32768 * 384 + 255) / 256, 256>>>(content, motion, a1hi, a1lo);
    prep_w<<<(256 * 384 + 255) / 256, 256>>>(W1, w1hi, w1lo, 256, 384);
    prep_w<<<(512 * 256 + 255) / 256, 256>>>(W2, w2hi, w2lo, 512, 256);
    prep_w<<<(1152 * 512 + 255) / 256, 256>>>(W3, w3hi, w3lo, 1152, 512);

    // ---- GEMM chain ----
    gemm_hmma<384, 256, true, false><<<dim3(2, 256), 256>>>(
        a1hi, a1lo, w1hi, w1lo, b1, nullptr, h1hi, h1lo);
    gemm_hmma<256, 512, true, false><<<dim3(4, 256), 256>>>(
        h1hi, h1lo, w2hi, w2lo, b2, nullptr, h2hi, h2lo);
    gemm_hmma<512, 1152, false, true><<<dim3(9, 256), 256>>>(
        h2hi, h2lo, w3hi, w3lo, b3, out, nullptr, nullptr);
}